// round 12
// baseline (speedup 1.0000x reference)
#include <cuda_runtime.h>
#include <math.h>

#define VV 50257
#define EE 300
#define HH 600
#define HD 300
#define LL 60
#define ZZ 100
#define T_IN 48
#define T_OUT 60
#define EOS_TOK 1

#define OFF_MEAN (T_OUT * VV)
#define OFF_LOGV (OFF_MEAN + LL * ZZ)

#define G_CTAS 148
#define S_CTAS 40
#define H_CTAS 108
#define NT 512
#define NW 16

// smem layout (floats) — 220160 bytes total
#define SM_ATW 0          // 36000: attn_W[:,300:900] staged fp32
#define SM_M 36000        // 18000
#define SM_H 54000        // 608
#define SM_O 54608        // 304
#define SM_AWV 54912      // 64
#define SM_S 54976        // 64
#define SMEM_FLOATS 55040
#define SMEM_BYTES (SMEM_FLOATS * 4)

// gemm: 3 bands (30/20/10 timesteps); aliases sm[0..6510] (helpers / post-decoder only)
#define NBLK 99
#define SM_RED 6000
#define SM_TMAX 6480

// lsm split
#define VHALF 25129

// ---------------- device scratch ----------------
__device__ float g_h[2][2][HD];
__device__ float g_enc_gi[2][T_IN * 900];
__device__ float g_enc_out[LL * HH];
__device__ float g_M[LL * EE];
__device__ float g_C[ZZ * EE];
__device__ float g_d[EE];
__device__ float g_l2hT[ZZ * HH];
__device__ float g_attn_x[T_OUT * LL];
__device__ float g_comb_x[T_OUT * EE];
__device__ float g_hT[HH * 64];
__device__ float g_logits[T_OUT * VV];
__device__ float g_pmax[T_OUT * NBLK];
__device__ float g_psum[T_OUT * NBLK];
__device__ unsigned g_bar;
__device__ unsigned g_barE[2];
__device__ unsigned g_step;
__device__ unsigned g_prep;
__device__ unsigned g_pc;
__device__ unsigned g_bdone[3];

// ---------------- helpers ----------------
__device__ __forceinline__ float wsum(float v) {
#pragma unroll
    for (int o = 16; o; o >>= 1) v += __shfl_xor_sync(0xffffffffu, v, o);
    return v;
}
__device__ __forceinline__ float wmax(float v) {
#pragma unroll
    for (int o = 16; o; o >>= 1) v = fmaxf(v, __shfl_xor_sync(0xffffffffu, v, o));
    return v;
}
__device__ __forceinline__ float sigm(float x) { return 1.0f / (1.0f + expf(-x)); }

__device__ __forceinline__ unsigned ldacq(unsigned* p) {
    unsigned v;
    asm volatile("ld.acquire.gpu.u32 %0, [%1];" : "=r"(v) : "l"(p) : "memory");
    return v;
}
__device__ __forceinline__ void strel(unsigned* p, unsigned v) {
    asm volatile("st.release.gpu.u32 [%0], %1;" :: "l"(p), "r"(v) : "memory");
}
__device__ __forceinline__ void redrel(unsigned* p) {
    asm volatile("red.release.gpu.add.u32 [%0], 1;" :: "l"(p) : "memory");
}
__device__ __forceinline__ void gbar_n(unsigned* ctr, int n, unsigned& tgt) {
    __syncthreads();
    tgt += n;
    if (threadIdx.x == 0) {
        redrel(ctr);
        while (ldacq(ctr) < tgt) {}
    }
    __syncthreads();
}
__device__ __forceinline__ void cta_wait(unsigned* ctr, unsigned val) {
    __syncthreads();
    if (threadIdx.x == 0) {
        while (ldacq(ctr) < val) __nanosleep(200);
    }
    __syncthreads();
}

// packed f32x2 helpers
__device__ __forceinline__ unsigned long long packf2(float lo, float hi) {
    unsigned long long r;
    asm("mov.b64 %0, {%1, %2};" : "=l"(r) : "f"(lo), "f"(hi));
    return r;
}
__device__ __forceinline__ void ffma2(unsigned long long& d, unsigned long long a, unsigned long long b) {
    asm("fma.rn.f32x2 %0, %1, %2, %0;" : "+l"(d) : "l"(a), "l"(b));
}
__device__ __forceinline__ float2 unpackf2(unsigned long long v) {
    float lo, hi;
    asm("mov.b64 {%0, %1}, %2;" : "=f"(lo), "=f"(hi) : "l"(v));
    return make_float2(lo, hi);
}

// ---------------- init ----------------
__global__ void init_kernel() {
    int tid = threadIdx.x;
    if (tid == 0) {
        g_bar = 0u; g_barE[0] = 0u; g_barE[1] = 0u;
        g_prep = 0u; g_pc = 0u; g_step = 0u;
        g_bdone[0] = 0u; g_bdone[1] = 0u; g_bdone[2] = 0u;
    }
    for (int i = tid; i < 2 * 2 * HD; i += blockDim.x) (&g_h[0][0][0])[i] = 0.0f;
    for (int i = tid; i < (LL - T_IN) * HH; i += blockDim.x) g_enc_out[T_IN * HH + i] = 0.0f;
}

// ---------------- seq mini-prep: group grp computes gi[grp] for t<8 ----------------
__device__ void mini_prep(int grp, int cta_in_grp,
                          const int* __restrict__ input, const float* __restrict__ emb,
                          const float* __restrict__ W, const float* __restrict__ bvec)
{
    const int lane = threadIdx.x & 31;
    int gw0 = cta_in_grp * NW + (threadIdx.x >> 5);
    for (int row = gw0; row < 900; row += 20 * NW) {
        float bi = bvec[row];
        float wr[10];
#pragma unroll
        for (int i = 0; i < 10; i++) {
            int k = lane + 32 * i;
            wr[i] = (k < EE) ? W[row * EE + k] : 0.0f;
        }
        for (int t = 0; t < 8; t++) {
            const float* x = emb + (long)input[t] * EE;
            float a = 0.0f;
#pragma unroll
            for (int i = 0; i < 10; i++) {
                int k = lane + 32 * i;
                if (k < EE) a = fmaf(wr[i], x[k], a);
            }
            a = wsum(a);
            if (lane == 0) g_enc_gi[grp][t * 900 + row] = a + bi;
        }
    }
}

// ---------------- phase A: prep tasks (HELPER CTAs only) ----------------
#define NTASKA 13078
__device__ void phaseA(const int* __restrict__ input, const int* __restrict__ target,
                       const float* __restrict__ emb,
                       const float* __restrict__ eWf, const float* __restrict__ ebf,
                       const float* __restrict__ eWb, const float* __restrict__ ebb,
                       const float* __restrict__ attn_W, const float* __restrict__ attn_b,
                       const float* __restrict__ comb_W, const float* __restrict__ comb_b,
                       const float* __restrict__ l2h_W)
{
    const int lane = threadIdx.x & 31;
    const int gw = (blockIdx.x - S_CTAS) * NW + (threadIdx.x >> 5);
    for (int task = gw; task < NTASKA; task += H_CTAS * NW) {
        if (task < 10800) {
            int rowid = task / 6, tb = task % 6;
            int dir = rowid / 900, row = rowid % 900;
            const float* W = dir ? eWb : eWf;
            float bi = (dir ? ebb : ebf)[row];
            float wr[10];
#pragma unroll
            for (int i = 0; i < 10; i++) {
                int k = lane + 32 * i;
                wr[i] = (k < EE) ? W[row * EE + k] : 0.0f;
            }
            for (int t = tb * 8; t < tb * 8 + 8; t++) {
                const float* x = emb + (long)input[t] * EE;
                float a = 0.0f;
#pragma unroll
                for (int i = 0; i < 10; i++) {
                    int k = lane + 32 * i;
                    if (k < EE) a = fmaf(wr[i], x[k], a);
                }
                a = wsum(a);
                if (lane == 0) g_enc_gi[dir][t * 900 + row] = a + bi;
            }
        } else if (task < 11160) {
            int id = task - 10800;
            int l = id / 6, tb = id % 6;
            float bi = attn_b[l];
            float wr[10];
#pragma unroll
            for (int i = 0; i < 10; i++) {
                int k = lane + 32 * i;
                wr[i] = (k < EE) ? attn_W[l * 900 + k] : 0.0f;
            }
            for (int t = tb * 10; t < tb * 10 + 10; t++) {
                int tok = (t == 0) ? EOS_TOK : target[t - 1];
                const float* x = emb + (long)tok * EE;
                float a = 0.0f;
#pragma unroll
                for (int i = 0; i < 10; i++) {
                    int k = lane + 32 * i;
                    if (k < EE) a = fmaf(wr[i], x[k], a);
                }
                a = wsum(a);
                if (lane == 0) g_attn_x[t * LL + l] = a + bi;
            }
        } else if (task < 12960) {
            int id = task - 11160;
            int e = id / 6, tb = id % 6;
            float bi = comb_b[e];
            float wr[10];
#pragma unroll
            for (int i = 0; i < 10; i++) {
                int k = lane + 32 * i;
                wr[i] = (k < EE) ? comb_W[e * 900 + k] : 0.0f;
            }
            for (int t = tb * 10; t < tb * 10 + 10; t++) {
                int tok = (t == 0) ? EOS_TOK : target[t - 1];
                const float* x = emb + (long)tok * EE;
                float a = 0.0f;
#pragma unroll
                for (int i = 0; i < 10; i++) {
                    int k = lane + 32 * i;
                    if (k < EE) a = fmaf(wr[i], x[k], a);
                }
                a = wsum(a);
                if (lane == 0) g_comb_x[t * EE + e] = a + bi;
            }
        } else {
            int base = (task - 12960) * 512;
            for (int i2 = base + lane; i2 < base + 512 && i2 < ZZ * HH; i2 += 32) {
                int h = i2 / ZZ, k = i2 % ZZ;
                g_l2hT[k * HH + h] = l2h_W[i2];
            }
        }
    }
}

// ---------------- prepC (helper CTAs) ----------------
__device__ void prepC(const float* __restrict__ comb_W, const float* __restrict__ l2h_b) {
    const int lane = threadIdx.x & 31;
    int gw = (blockIdx.x - S_CTAS) * NW + (threadIdx.x >> 5);
    for (int task = gw; task < 30300; task += H_CTAS * NW) {
        if (task < 30000) {
            int e = task / ZZ, k = task % ZZ;
            const float* cw = comb_W + e * 900 + EE;
            const float* lt = g_l2hT + k * HH;
            float a = 0.0f;
            for (int h = lane; h < HH; h += 32) a = fmaf(cw[h], lt[h], a);
            a = wsum(a);
            if (lane == 0) g_C[k * EE + e] = a;
        } else {
            int e = task - 30000;
            const float* cw = comb_W + e * 900 + EE;
            float a = 0.0f;
            for (int h = lane; h < HH; h += 32) a = fmaf(cw[h], l2h_b[h], a);
            a = wsum(a);
            if (lane == 0) g_d[e] = a;
        }
    }
}

// ---------------- GEMM band tile (templated width) with partial softmax ----------------
template<int TB>
__device__ void gemm_band_t(float* sm, int t0, int blk,
                            const float* __restrict__ out_W, const float* __restrict__ out_b)
{
    constexpr int NP = TB / 2;
    unsigned long long* s_ht = (unsigned long long*)sm;
    float* s_red = sm + SM_RED;
    float* s_tmax = sm + SM_TMAX;
    const int tid = threadIdx.x;
    const int lane = tid & 31;
    const int warp = tid >> 5;
    const int v = blk * NT + tid;
    const bool ok = v < VV;
    const int vc = ok ? v : 0;

    unsigned long long acc[NP];
    float b0 = out_b[vc];
#pragma unroll
    for (int m = 0; m < NP; m++) acc[m] = packf2(b0, b0);

    const float4* w4 = (const float4*)(out_W + (long)vc * HH);

    for (int chunk = 0; chunk < 3; chunk++) {
        const int k0 = chunk * 200;
        for (int i = tid; i < 200 * NP; i += NT) {
            int k_local = i / NP, m = i % NP;
            float2 hv = *(const float2*)(g_hT + (k0 + k_local) * 64 + t0 + 2 * m);
            s_ht[i] = packf2(hv.x, hv.y);
        }
        __syncthreads();

#pragma unroll 2
        for (int c4 = 0; c4 < 50; c4++) {
            float4 w = w4[chunk * 50 + c4];
            unsigned long long w2[4];
            w2[0] = packf2(w.x, w.x); w2[1] = packf2(w.y, w.y);
            w2[2] = packf2(w.z, w.z); w2[3] = packf2(w.w, w.w);
#pragma unroll
            for (int kk = 0; kk < 4; kk++) {
                const unsigned long long* hp = s_ht + (c4 * 4 + kk) * NP;
#pragma unroll
                for (int m = 0; m < NP; m++) ffma2(acc[m], w2[kk], hp[m]);
            }
        }
        __syncthreads();
    }

#pragma unroll
    for (int m = 0; m < NP; m++) {
        float2 p = unpackf2(acc[m]);
        if (ok) {
            g_logits[(long)(t0 + 2 * m) * VV + v] = p.x;
            g_logits[(long)(t0 + 2 * m + 1) * VV + v] = p.y;
        } else { p.x = -3.0e38f; p.y = -3.0e38f; }
        float mlo = wmax(p.x), mhi = wmax(p.y);
        if (lane == 0) {
            s_red[warp * TB + 2 * m] = mlo;
            s_red[warp * TB + 2 * m + 1] = mhi;
        }
    }
    __syncthreads();
    if (tid < TB) {
        float mx = -3.0e38f;
        for (int w = 0; w < 16; w++) mx = fmaxf(mx, s_red[w * TB + tid]);
        s_tmax[tid] = mx;
        g_pmax[(t0 + tid) * NBLK + blk] = mx;
    }
    __syncthreads();
#pragma unroll
    for (int m = 0; m < NP; m++) {
        float2 p = unpackf2(acc[m]);
        float elo = ok ? expf(p.x - s_tmax[2 * m]) : 0.0f;
        float ehi = ok ? expf(p.y - s_tmax[2 * m + 1]) : 0.0f;
        float slo = wsum(elo), shi = wsum(ehi);
        if (lane == 0) {
            s_red[warp * TB + 2 * m] = slo;
            s_red[warp * TB + 2 * m + 1] = shi;
        }
    }
    __syncthreads();
    if (tid < TB) {
        float s = 0.0f;
        for (int w = 0; w < 16; w++) s += s_red[w * TB + tid];
        g_psum[(t0 + tid) * NBLK + blk] = s;
    }
    __syncthreads();
}

// ---------------- final log_softmax half-row ----------------
__device__ void lsm_row_half(int r, int half, float* __restrict__ out, float* sm) {
    const int tid = threadIdx.x;
    float* sred = sm;

    float mloc = (tid < NBLK) ? __ldcg(&g_pmax[r * NBLK + tid]) : -3.0e38f;
    float m = wmax(mloc);
    if ((tid & 31) == 0) sred[tid >> 5] = m;
    __syncthreads();
    if (tid < 32) {
        float mm = (tid < NW) ? sred[tid] : -3.0e38f;
        mm = wmax(mm);
        if (tid == 0) sred[0] = mm;
    }
    __syncthreads();
    m = sred[0];
    __syncthreads();

    float sloc = (tid < NBLK) ? __ldcg(&g_psum[r * NBLK + tid]) * expf(mloc - m) : 0.0f;
    float ssum = wsum(sloc);
    if ((tid & 31) == 0) sred[tid >> 5] = ssum;
    __syncthreads();
    if (tid < 32) {
        float ss = (tid < NW) ? sred[tid] : 0.0f;
        ss = wsum(ss);
        if (tid == 0) sred[0] = m + logf(ss);
    }
    __syncthreads();
    float base = sred[0];

    const float* row = g_logits + (long)r * VV;
    float* orow = out + (long)r * VV;
    int v0 = half * VHALF;
    int v1 = half ? VV : VHALF;
    for (int v = v0 + tid; v < v1; v += NT) orow[v] = __ldcg(row + v) - base;
}

// ---------------- the mega kernel ----------------
__global__ __launch_bounds__(NT, 1) void mega_kernel(
    const int* __restrict__ input, const int* __restrict__ target,
    const float* __restrict__ eps, const float* __restrict__ emb,
    const float* __restrict__ encWih_f, const float* __restrict__ encWhh_f,
    const float* __restrict__ encbih_f, const float* __restrict__ encbhh_f,
    const float* __restrict__ encWih_b, const float* __restrict__ encWhh_b,
    const float* __restrict__ encbih_b, const float* __restrict__ encbhh_b,
    const float* __restrict__ decWih_f, const float* __restrict__ decWhh_f,
    const float* __restrict__ decbih_f, const float* __restrict__ decbhh_f,
    const float* __restrict__ decWih_b, const float* __restrict__ decWhh_b,
    const float* __restrict__ decbih_b, const float* __restrict__ decbhh_b,
    const float* __restrict__ h2m_W, const float* __restrict__ h2m_b,
    const float* __restrict__ h2v_W, const float* __restrict__ h2v_b,
    const float* __restrict__ l2h_W, const float* __restrict__ l2h_b,
    const float* __restrict__ attn_W, const float* __restrict__ attn_b,
    const float* __restrict__ comb_W, const float* __restrict__ comb_b,
    const float* __restrict__ out_W, const float* __restrict__ out_b,
    float* __restrict__ out)
{
    extern __shared__ float sm[];
    float* s_M = sm + SM_M;
    float* s_h = sm + SM_H;
    float* s_o = sm + SM_O;
    float* s_aw = sm + SM_AWV;
    float* s_s = sm + SM_S;

    const int tid = threadIdx.x;
    const int lane = tid & 31;
    const int warp = tid >> 5;
    unsigned tgt = 0, tgtE = 0, tgtP = 0;
    float* hbuf = (float*)g_h;

    if (blockIdx.x < S_CTAS) {
        // ================= SEQ ROLE (CTAs 0..39) =================
        const int grp = blockIdx.x / 20;
        const int cig = blockIdx.x % 20;
        const bool isGate = (warp >= 1);
        int gr = blockIdx.x * 15 + (warp - 1);
        int dir = 0, j = 0;
        if (isGate) { dir = gr / HD; j = gr % HD; }

        // mini-prep: own group's gi for t<8, then group barrier
        mini_prep(grp, cig, input, emb,
                  grp ? encWih_b : encWih_f, grp ? encbih_b : encbih_f);
        gbar_n(&g_barE[grp], 20, tgtE);

        float wA[30], wB[30];
        float ebr = 0, ebz = 0, ebn = 0;

        if (isGate) {
            const float* W = dir ? encWhh_b : encWhh_f;
            const float* bh = dir ? encbhh_b : encbhh_f;
#pragma unroll
            for (int i = 0; i < 10; i++) {
                int k = lane + 32 * i;
                bool ok = k < HD;
                wA[i]      = ok ? W[j * HD + k] : 0.0f;
                wA[10 + i] = ok ? W[(HD + j) * HD + k] : 0.0f;
                wA[20 + i] = ok ? W[(2 * HD + j) * HD + k] : 0.0f;
            }
            ebr = bh[j]; ebz = bh[HD + j]; ebn = bh[2 * HD + j];
        }

        // ---- encoder: 48 steps ----
        for (int t = 0; t < T_IN; t++) {
            if (t == 8) cta_wait(&g_prep, (unsigned)H_CTAS);
            const int p = t & 1, q = p ^ 1;
            float gi0 = 0, gi1 = 0, gi2 = 0;
            if (isGate && lane == 0) {
                const float* gi = g_enc_gi[grp] + t * 900;
                gi0 = gi[j]; gi1 = gi[HD + j]; gi2 = gi[2 * HD + j];
            }
            if (tid < 75) ((float4*)s_h)[tid] = __ldcg((const float4*)(hbuf + p * HH + grp * HD) + tid);
            __syncthreads();
            if (isGate) {
                float ar = 0, az = 0, an = 0;
#pragma unroll
                for (int i = 0; i < 10; i++) {
                    int k = lane + 32 * i;
                    if (k < HD) {
                        float hv = s_h[k];
                        ar = fmaf(wA[i], hv, ar);
                        az = fmaf(wA[10 + i], hv, az);
                        an = fmaf(wA[20 + i], hv, an);
                    }
                }
                ar = wsum(ar); az = wsum(az); an = wsum(an);
                if (lane == 0) {
                    float r = sigm(gi0 + ar + ebr);
                    float zg = sigm(gi1 + az + ebz);
                    float nn = tanhf(gi2 + r * (an + ebn));
                    float hn = (1.0f - zg) * nn + zg * s_h[j];
                    hbuf[q * HH + grp * HD + j] = hn;
                    g_enc_out[t * HH + grp * HD + j] = hn;
                }
            }
            gbar_n(&g_barE[grp], 20, tgtE);
        }

        gbar_n(&g_bar, S_CTAS, tgt);   // g_bar = 40

        // ---- preload decoder weights ----
        float dbhr = 0, dbhz = 0, dbhn = 0, dbir = 0, dbiz = 0, dbin = 0;
        if (isGate) {
            const float* Wh = dir ? decWhh_b : decWhh_f;
            const float* Wi = dir ? decWih_b : decWih_f;
#pragma unroll
            for (int i = 0; i < 10; i++) {
                int k = lane + 32 * i;
                bool ok = k < HD;
                wA[i]      = ok ? Wh[j * HD + k] : 0.0f;
                wA[10 + i] = ok ? Wh[(HD + j) * HD + k] : 0.0f;
                wA[20 + i] = ok ? Wh[(2 * HD + j) * HD + k] : 0.0f;
                wB[i]      = ok ? Wi[j * EE + k] : 0.0f;
                wB[10 + i] = ok ? Wi[(EE + j) * EE + k] : 0.0f;
                wB[20 + i] = ok ? Wi[(2 * EE + j) * EE + k] : 0.0f;
            }
            const float* bh = dir ? decbhh_b : decbhh_f;
            const float* bi = dir ? decbih_b : decbih_f;
            dbhr = bh[j]; dbhz = bh[HD + j]; dbhn = bh[2 * HD + j];
            dbir = bi[j]; dbiz = bi[HD + j]; dbin = bi[2 * HD + j];
        }

        // ---- VAE fused ----
        cta_wait(&g_pc, H_CTAS);
        for (int l = blockIdx.x; l < LL; l += S_CTAS) {
            for (int i = tid; i < HH; i += NT) s_h[i] = __ldcg(g_enc_out + l * HH + i);
            __syncthreads();
            for (int zi = warp; zi < ZZ; zi += NW) {
                float am = 0, av = 0;
                for (int k = lane; k < HH; k += 32) {
                    float e = s_h[k];
                    am = fmaf(h2m_W[zi * HH + k], e, am);
                    av = fmaf(h2v_W[zi * HH + k], e, av);
                }
                am = wsum(am); av = wsum(av);
                if (lane == 0) {
                    am += h2m_b[zi]; av += h2v_b[zi];
                    out[OFF_MEAN + l * ZZ + zi] = am;
                    out[OFF_LOGV + l * ZZ + zi] = av;
                    s_o[zi] = eps[l * ZZ + zi] * expf(0.5f * av) + am;
                }
            }
            __syncthreads();
            for (int e = tid; e < EE; e += NT) {
                float a = g_d[e];
#pragma unroll 4
                for (int k = 0; k < ZZ; k++) a = fmaf(s_o[k], g_C[k * EE + e], a);
                g_M[l * EE + e] = a;
            }
            __syncthreads();
        }
        gbar_n(&g_bar, S_CTAS, tgt);   // g_bar = 80

        // stage M + attn weights into SMEM once
        for (int i = tid; i < LL * EE; i += NT) s_M[i] = __ldcg(g_M + i);
        for (int idx = tid; idx < LL * 150; idx += NT) {
            int l = idx / 150, c4 = idx % 150;
            ((float4*)(sm + SM_ATW))[idx] = ((const float4*)(attn_W + l * 900 + EE))[c4];
        }

        // ---- decoder: 60 steps, 1 barrier each ----
        for (int t = 0; t < T_OUT; t++) {
            const int p = t & 1, q = p ^ 1;
            float cx = 0;
            if (tid < EE) cx = g_comb_x[t * EE + tid];
            if (tid < 150) ((float4*)s_h)[tid] = __ldcg((const float4*)(hbuf + p * HH) + tid);
            __syncthreads();

            // attention: weights from SMEM, h chunks register-cached per warp
            const float4* sh4 = (const float4*)s_h;
            const float4* atw = (const float4*)(sm + SM_ATW);
            float4 h4r[5];
#pragma unroll
            for (int i = 0; i < 5; i++) {
                int c = lane + 32 * i;
                h4r[i] = (c < 150) ? sh4[c] : make_float4(0.f, 0.f, 0.f, 0.f);
            }
#pragma unroll
            for (int rr = 0; rr < 4; rr++) {
                int l = warp + 16 * rr;
                if (l < LL) {
                    float axv = g_attn_x[t * LL + l];
                    float a = 0;
#pragma unroll
                    for (int i = 0; i < 5; i++) {
                        int c = lane + 32 * i;
                        if (c < 150) {
                            float4 w = atw[l * 150 + c];
                            a = fmaf(w.x, h4r[i].x, fmaf(w.y, h4r[i].y, fmaf(w.z, h4r[i].z, fmaf(w.w, h4r[i].w, a))));
                        }
                    }
                    a = wsum(a);
                    if (lane == 0) s_s[l] = a + axv;
                }
            }
            __syncthreads();

            float ghr = 0, ghz = 0, ghn = 0;
            if (warp == 0) {
                float v0 = s_s[lane];
                float v1 = (lane + 32 < LL) ? s_s[lane + 32] : -1e30f;
                float m = wmax(fmaxf(v0, v1));
                float e0 = expf(v0 - m);
                float e1 = (lane + 32 < LL) ? expf(v1 - m) : 0.0f;
                float inv = 1.0f / wsum(e0 + e1);
                s_aw[lane] = e0 * inv;
                if (lane + 32 < LL) s_aw[lane + 32] = e1 * inv;
            } else {
                const float* hs = s_h + dir * HD;
                float ar = 0, az = 0, an = 0;
#pragma unroll
                for (int i = 0; i < 10; i++) {
                    int k = lane + 32 * i;
                    if (k < HD) {
                        float hv = hs[k];
                        ar = fmaf(wA[i], hv, ar);
                        az = fmaf(wA[10 + i], hv, az);
                        an = fmaf(wA[20 + i], hv, an);
                    }
                }
                ar = wsum(ar); az = wsum(az); an = wsum(an);
                ghr = ar + dbhr; ghz = az + dbhz; ghn = an + dbhn;
            }
            __syncthreads();

            if (tid < EE) {
                float acc0 = cx, acc1 = 0.f;
#pragma unroll
                for (int l = 0; l < LL; l += 2) {
                    acc0 = fmaf(s_aw[l], s_M[l * EE + tid], acc0);
                    acc1 = fmaf(s_aw[l + 1], s_M[(l + 1) * EE + tid], acc1);
                }
                s_o[tid] = fmaxf(acc0 + acc1, 0.0f);
            }
            __syncthreads();

            if (isGate) {
                float br = 0, bz = 0, bn = 0;
#pragma unroll
                for (int i = 0; i < 10; i++) {
                    int k = lane + 32 * i;
                    if (k < EE) {
                        float ov = s_o[k];
                        br = fmaf(wB[i], ov, br);
                        bz = fmaf(wB[10 + i], ov, bz);
                        bn = fmaf(wB[20 + i], ov, bn);
                    }
                }
                br = wsum(br); bz = wsum(bz); bn = wsum(bn);
                if (lane == 0) {
                    float r = sigm(br + dbir + ghr);
                    float zg = sigm(bz + dbiz + ghz);
                    float nn = tanhf(bn + dbin + r * ghn);
                    float hn = (1.0f - zg) * nn + zg * s_h[dir * HD + j];
                    hbuf[q * HH + dir * HD + j] = hn;
                    g_hT[(dir * HD + j) * 64 + t] = hn;
                }
            }
            gbar_n(&g_bar, S_CTAS, tgt);
            if (blockIdx.x == 0 && tid == 0) strel(&g_step, (unsigned)(t + 1));
        }
    } else {
        // ================= HELPER ROLE (CTAs 40..147) =================
        phaseA(input, target, emb, encWih_f, encbih_f, encWih_b, encbih_b,
               attn_W, attn_b, comb_W, comb_b, l2h_W);
        gbar_n(&g_prep, H_CTAS, tgtP);

        prepC(comb_W, l2h_b);
        __syncthreads();
        if (tid == 0) redrel(&g_pc);

        // bands 0 (t0..29 @step30) and 1 (t30..49 @step50)
        int hid = blockIdx.x - S_CTAS;
        for (int idx = hid; idx < 2 * NBLK; idx += H_CTAS) {
            if (idx < NBLK) {
                cta_wait(&g_step, 30u);
                gemm_band_t<30>(sm, 0, idx, out_W, out_b);
                if (tid == 0) redrel(&g_bdone[0]);
            } else {
                cta_wait(&g_step, 50u);
                gemm_band_t<20>(sm, 30, idx - NBLK, out_W, out_b);
                if (tid == 0) redrel(&g_bdone[1]);
            }
        }
    }

    // ======== band 2 (t50..59, ALL CTAs, after full decoder) ========
    for (int blk = blockIdx.x; blk < NBLK; blk += G_CTAS) {
        cta_wait(&g_step, (unsigned)T_OUT);
        gemm_band_t<10>(sm, 50, blk, out_W, out_b);
        if (tid == 0) redrel(&g_bdone[2]);
    }

    // ======== log_softmax: 120 CTAs, half-row each ========
    if (blockIdx.x < 2 * T_OUT) {
        int r = blockIdx.x >> 1;
        int half = blockIdx.x & 1;
        int band = (r < 30) ? 0 : ((r < 50) ? 1 : 2);
        cta_wait(&g_bdone[band], NBLK);
        lsm_row_half(r, half, out, sm);
    }
}

extern "C" void kernel_launch(void* const* d_in, const int* in_sizes, int n_in,
                              void* d_out, int out_size) {
    const int* input = (const int*)d_in[0];
    const int* target = (const int*)d_in[1];
    const float* eps = (const float*)d_in[2];
    const float* emb = (const float*)d_in[3];
    const float* encWih_f = (const float*)d_in[4];
    const float* encWhh_f = (const float*)d_in[5];
    const float* encbih_f = (const float*)d_in[6];
    const float* encbhh_f = (const float*)d_in[7];
    const float* encWih_b = (const float*)d_in[8];
    const float* encWhh_b = (const float*)d_in[9];
    const float* encbih_b = (const float*)d_in[10];
    const float* encbhh_b = (const float*)d_in[11];
    const float* decWih_f = (const float*)d_in[12];
    const float* decWhh_f = (const float*)d_in[13];
    const float* decbih_f = (const float*)d_in[14];
    const float* decbhh_f = (const float*)d_in[15];
    const float* decWih_b = (const float*)d_in[16];
    const float* decWhh_b = (const float*)d_in[17];
    const float* decbih_b = (const float*)d_in[18];
    const float* decbhh_b = (const float*)d_in[19];
    const float* h2m_W = (const float*)d_in[20];
    const float* h2m_b = (const float*)d_in[21];
    const float* h2v_W = (const float*)d_in[22];
    const float* h2v_b = (const float*)d_in[23];
    const float* l2h_W = (const float*)d_in[24];
    const float* l2h_b = (const float*)d_in[25];
    const float* attn_W = (const float*)d_in[26];
    const float* attn_b = (const float*)d_in[27];
    const float* comb_W = (const float*)d_in[28];
    const float* comb_b = (const float*)d_in[29];
    const float* out_W = (const float*)d_in[30];
    const float* out_b = (const float*)d_in[31];
    float* out = (float*)d_out;

    cudaFuncSetAttribute(mega_kernel, cudaFuncAttributeMaxDynamicSharedMemorySize,
                         SMEM_BYTES);

    init_kernel<<<1, 256>>>();
    mega_kernel<<<G_CTAS, NT, SMEM_BYTES>>>(
        input, target, eps, emb,
        encWih_f, encWhh_f, encbih_f, encbhh_f,
        encWih_b, encWhh_b, encbih_b, encbhh_b,
        decWih_f, decWhh_f, decbih_f, decbhh_f,
        decWih_b, decWhh_b, decbih_b, decbhh_b,
        h2m_W, h2m_b, h2v_W, h2v_b, l2h_W, l2h_b,
        attn_W, attn_b, comb_W, comb_b, out_W, out_b, out);
}

// round 13
// speedup vs baseline: 1.3358x; 1.3358x over previous
#include <cuda_runtime.h>
#include <math.h>

#define VV 50257
#define EE 300
#define HH 600
#define HD 300
#define LL 60
#define ZZ 100
#define T_IN 48
#define T_OUT 60
#define EOS_TOK 1

#define OFF_MEAN (T_OUT * VV)
#define OFF_LOGV (OFF_MEAN + LL * ZZ)

#define G_CTAS 148
#define S_CTAS 40
#define H_CTAS 108
#define NT 512
#define NW 16

// smem layout (floats) — 76KB total (L1D stays ~150KB)
#define SM_M 0
#define SM_H 18000
#define SM_O 18608
#define SM_AWV 18912
#define SM_S 18976
#define SMEM_FLOATS 19040
#define SMEM_BYTES (SMEM_FLOATS * 4)

// gemm: 3 bands (30/20/10 timesteps); aliases sm[0..6510]
#define NBLK 99
#define SM_RED 6000
#define SM_TMAX 6480

// lsm split
#define VHALF 25129

// ---------------- device scratch ----------------
__device__ float g_h[2][2][HD];
__device__ float g_enc_gi[2][T_IN * 900];
__device__ float g_enc_out[LL * HH];
__device__ float g_M[LL * EE];
__device__ float g_C[ZZ * EE];
__device__ float g_d[EE];
__device__ float g_l2hT[ZZ * HH];
__device__ float g_attn_x[T_OUT * LL];
__device__ float g_comb_x[T_OUT * EE];
__device__ float g_hT[HH * 64];
__device__ float g_logits[T_OUT * VV];
__device__ float g_pmax[T_OUT * NBLK];
__device__ float g_psum[T_OUT * NBLK];
__device__ unsigned g_bar;
__device__ unsigned g_barE[2];
__device__ unsigned g_step;
__device__ unsigned g_prep;
__device__ unsigned g_pc;
__device__ unsigned g_bdone[3];

// ---------------- helpers ----------------
__device__ __forceinline__ float wsum(float v) {
#pragma unroll
    for (int o = 16; o; o >>= 1) v += __shfl_xor_sync(0xffffffffu, v, o);
    return v;
}
__device__ __forceinline__ float wmax(float v) {
#pragma unroll
    for (int o = 16; o; o >>= 1) v = fmaxf(v, __shfl_xor_sync(0xffffffffu, v, o));
    return v;
}
__device__ __forceinline__ float sigm(float x) { return 1.0f / (1.0f + expf(-x)); }

__device__ __forceinline__ unsigned ldacq(unsigned* p) {
    unsigned v;
    asm volatile("ld.acquire.gpu.u32 %0, [%1];" : "=r"(v) : "l"(p) : "memory");
    return v;
}
__device__ __forceinline__ void strel(unsigned* p, unsigned v) {
    asm volatile("st.release.gpu.u32 [%0], %1;" :: "l"(p), "r"(v) : "memory");
}
__device__ __forceinline__ void redrel(unsigned* p) {
    asm volatile("red.release.gpu.add.u32 [%0], 1;" :: "l"(p) : "memory");
}
__device__ __forceinline__ void gbar_n(unsigned* ctr, int n, unsigned& tgt) {
    __syncthreads();
    tgt += n;
    if (threadIdx.x == 0) {
        redrel(ctr);
        while (ldacq(ctr) < tgt) {}
    }
    __syncthreads();
}
__device__ __forceinline__ void cta_wait(unsigned* ctr, unsigned val) {
    __syncthreads();
    if (threadIdx.x == 0) {
        while (ldacq(ctr) < val) __nanosleep(200);
    }
    __syncthreads();
}

// packed f32x2 helpers
__device__ __forceinline__ unsigned long long packf2(float lo, float hi) {
    unsigned long long r;
    asm("mov.b64 %0, {%1, %2};" : "=l"(r) : "f"(lo), "f"(hi));
    return r;
}
__device__ __forceinline__ void ffma2(unsigned long long& d, unsigned long long a, unsigned long long b) {
    asm("fma.rn.f32x2 %0, %1, %2, %0;" : "+l"(d) : "l"(a), "l"(b));
}
__device__ __forceinline__ float2 unpackf2(unsigned long long v) {
    float lo, hi;
    asm("mov.b64 {%0, %1}, %2;" : "=f"(lo), "=f"(hi) : "l"(v));
    return make_float2(lo, hi);
}

// ---------------- init ----------------
__global__ void init_kernel() {
    int tid = threadIdx.x;
    if (tid == 0) {
        g_bar = 0u; g_barE[0] = 0u; g_barE[1] = 0u;
        g_prep = 0u; g_pc = 0u; g_step = 0u;
        g_bdone[0] = 0u; g_bdone[1] = 0u; g_bdone[2] = 0u;
    }
    for (int i = tid; i < 2 * 2 * HD; i += blockDim.x) (&g_h[0][0][0])[i] = 0.0f;
    for (int i = tid; i < (LL - T_IN) * HH; i += blockDim.x) g_enc_out[T_IN * HH + i] = 0.0f;
}

// ---------------- seq mini-prep: group grp computes gi[grp] for t<8 ----------------
__device__ void mini_prep(int grp, int cta_in_grp,
                          const int* __restrict__ input, const float* __restrict__ emb,
                          const float* __restrict__ W, const float* __restrict__ bvec)
{
    const int lane = threadIdx.x & 31;
    int gw0 = cta_in_grp * NW + (threadIdx.x >> 5);
    for (int row = gw0; row < 900; row += 20 * NW) {
        float bi = bvec[row];
        float wr[10];
#pragma unroll
        for (int i = 0; i < 10; i++) {
            int k = lane + 32 * i;
            wr[i] = (k < EE) ? W[row * EE + k] : 0.0f;
        }
        for (int t = 0; t < 8; t++) {
            const float* x = emb + (long)input[t] * EE;
            float a = 0.0f;
#pragma unroll
            for (int i = 0; i < 10; i++) {
                int k = lane + 32 * i;
                if (k < EE) a = fmaf(wr[i], x[k], a);
            }
            a = wsum(a);
            if (lane == 0) g_enc_gi[grp][t * 900 + row] = a + bi;
        }
    }
}

// ---------------- phase A: prep tasks (HELPER CTAs only) ----------------
#define NTASKA 13078
__device__ void phaseA(const int* __restrict__ input, const int* __restrict__ target,
                       const float* __restrict__ emb,
                       const float* __restrict__ eWf, const float* __restrict__ ebf,
                       const float* __restrict__ eWb, const float* __restrict__ ebb,
                       const float* __restrict__ attn_W, const float* __restrict__ attn_b,
                       const float* __restrict__ comb_W, const float* __restrict__ comb_b,
                       const float* __restrict__ l2h_W)
{
    const int lane = threadIdx.x & 31;
    const int gw = (blockIdx.x - S_CTAS) * NW + (threadIdx.x >> 5);
    for (int task = gw; task < NTASKA; task += H_CTAS * NW) {
        if (task < 10800) {
            int rowid = task / 6, tb = task % 6;
            int dir = rowid / 900, row = rowid % 900;
            const float* W = dir ? eWb : eWf;
            float bi = (dir ? ebb : ebf)[row];
            float wr[10];
#pragma unroll
            for (int i = 0; i < 10; i++) {
                int k = lane + 32 * i;
                wr[i] = (k < EE) ? W[row * EE + k] : 0.0f;
            }
            for (int t = tb * 8; t < tb * 8 + 8; t++) {
                const float* x = emb + (long)input[t] * EE;
                float a = 0.0f;
#pragma unroll
                for (int i = 0; i < 10; i++) {
                    int k = lane + 32 * i;
                    if (k < EE) a = fmaf(wr[i], x[k], a);
                }
                a = wsum(a);
                if (lane == 0) g_enc_gi[dir][t * 900 + row] = a + bi;
            }
        } else if (task < 11160) {
            int id = task - 10800;
            int l = id / 6, tb = id % 6;
            float bi = attn_b[l];
            float wr[10];
#pragma unroll
            for (int i = 0; i < 10; i++) {
                int k = lane + 32 * i;
                wr[i] = (k < EE) ? attn_W[l * 900 + k] : 0.0f;
            }
            for (int t = tb * 10; t < tb * 10 + 10; t++) {
                int tok = (t == 0) ? EOS_TOK : target[t - 1];
                const float* x = emb + (long)tok * EE;
                float a = 0.0f;
#pragma unroll
                for (int i = 0; i < 10; i++) {
                    int k = lane + 32 * i;
                    if (k < EE) a = fmaf(wr[i], x[k], a);
                }
                a = wsum(a);
                if (lane == 0) g_attn_x[t * LL + l] = a + bi;
            }
        } else if (task < 12960) {
            int id = task - 11160;
            int e = id / 6, tb = id % 6;
            float bi = comb_b[e];
            float wr[10];
#pragma unroll
            for (int i = 0; i < 10; i++) {
                int k = lane + 32 * i;
                wr[i] = (k < EE) ? comb_W[e * 900 + k] : 0.0f;
            }
            for (int t = tb * 10; t < tb * 10 + 10; t++) {
                int tok = (t == 0) ? EOS_TOK : target[t - 1];
                const float* x = emb + (long)tok * EE;
                float a = 0.0f;
#pragma unroll
                for (int i = 0; i < 10; i++) {
                    int k = lane + 32 * i;
                    if (k < EE) a = fmaf(wr[i], x[k], a);
                }
                a = wsum(a);
                if (lane == 0) g_comb_x[t * EE + e] = a + bi;
            }
        } else {
            int base = (task - 12960) * 512;
            for (int i2 = base + lane; i2 < base + 512 && i2 < ZZ * HH; i2 += 32) {
                int h = i2 / ZZ, k = i2 % ZZ;
                g_l2hT[k * HH + h] = l2h_W[i2];
            }
        }
    }
}

// ---------------- prepC (helper CTAs) ----------------
__device__ void prepC(const float* __restrict__ comb_W, const float* __restrict__ l2h_b) {
    const int lane = threadIdx.x & 31;
    int gw = (blockIdx.x - S_CTAS) * NW + (threadIdx.x >> 5);
    for (int task = gw; task < 30300; task += H_CTAS * NW) {
        if (task < 30000) {
            int e = task / ZZ, k = task % ZZ;
            const float* cw = comb_W + e * 900 + EE;
            const float* lt = g_l2hT + k * HH;
            float a = 0.0f;
            for (int h = lane; h < HH; h += 32) a = fmaf(cw[h], lt[h], a);
            a = wsum(a);
            if (lane == 0) g_C[k * EE + e] = a;
        } else {
            int e = task - 30000;
            const float* cw = comb_W + e * 900 + EE;
            float a = 0.0f;
            for (int h = lane; h < HH; h += 32) a = fmaf(cw[h], l2h_b[h], a);
            a = wsum(a);
            if (lane == 0) g_d[e] = a;
        }
    }
}

// ---------------- GEMM band tile (templated width) with partial softmax ----------------
template<int TB>
__device__ void gemm_band_t(float* sm, int t0, int blk,
                            const float* __restrict__ out_W, const float* __restrict__ out_b)
{
    constexpr int NP = TB / 2;
    unsigned long long* s_ht = (unsigned long long*)sm;
    float* s_red = sm + SM_RED;
    float* s_tmax = sm + SM_TMAX;
    const int tid = threadIdx.x;
    const int lane = tid & 31;
    const int warp = tid >> 5;
    const int v = blk * NT + tid;
    const bool ok = v < VV;
    const int vc = ok ? v : 0;

    unsigned long long acc[NP];
    float b0 = out_b[vc];
#pragma unroll
    for (int m = 0; m < NP; m++) acc[m] = packf2(b0, b0);

    const float4* w4 = (const float4*)(out_W + (long)vc * HH);

    for (int chunk = 0; chunk < 3; chunk++) {
        const int k0 = chunk * 200;
        for (int i = tid; i < 200 * NP; i += NT) {
            int k_local = i / NP, m = i % NP;
            float2 hv = *(const float2*)(g_hT + (k0 + k_local) * 64 + t0 + 2 * m);
            s_ht[i] = packf2(hv.x, hv.y);
        }
        __syncthreads();

#pragma unroll 2
        for (int c4 = 0; c4 < 50; c4++) {
            float4 w = w4[chunk * 50 + c4];
            unsigned long long w2[4];
            w2[0] = packf2(w.x, w.x); w2[1] = packf2(w.y, w.y);
            w2[2] = packf2(w.z, w.z); w2[3] = packf2(w.w, w.w);
#pragma unroll
            for (int kk = 0; kk < 4; kk++) {
                const unsigned long long* hp = s_ht + (c4 * 4 + kk) * NP;
#pragma unroll
                for (int m = 0; m < NP; m++) ffma2(acc[m], w2[kk], hp[m]);
            }
        }
        __syncthreads();
    }

#pragma unroll
    for (int m = 0; m < NP; m++) {
        float2 p = unpackf2(acc[m]);
        if (ok) {
            g_logits[(long)(t0 + 2 * m) * VV + v] = p.x;
            g_logits[(long)(t0 + 2 * m + 1) * VV + v] = p.y;
        } else { p.x = -3.0e38f; p.y = -3.0e38f; }
        float mlo = wmax(p.x), mhi = wmax(p.y);
        if (lane == 0) {
            s_red[warp * TB + 2 * m] = mlo;
            s_red[warp * TB + 2 * m + 1] = mhi;
        }
    }
    __syncthreads();
    if (tid < TB) {
        float mx = -3.0e38f;
        for (int w = 0; w < 16; w++) mx = fmaxf(mx, s_red[w * TB + tid]);
        s_tmax[tid] = mx;
        g_pmax[(t0 + tid) * NBLK + blk] = mx;
    }
    __syncthreads();
#pragma unroll
    for (int m = 0; m < NP; m++) {
        float2 p = unpackf2(acc[m]);
        float elo = ok ? expf(p.x - s_tmax[2 * m]) : 0.0f;
        float ehi = ok ? expf(p.y - s_tmax[2 * m + 1]) : 0.0f;
        float slo = wsum(elo), shi = wsum(ehi);
        if (lane == 0) {
            s_red[warp * TB + 2 * m] = slo;
            s_red[warp * TB + 2 * m + 1] = shi;
        }
    }
    __syncthreads();
    if (tid < TB) {
        float s = 0.0f;
        for (int w = 0; w < 16; w++) s += s_red[w * TB + tid];
        g_psum[(t0 + tid) * NBLK + blk] = s;
    }
    __syncthreads();
}

// ---------------- final log_softmax half-row ----------------
__device__ void lsm_row_half(int r, int half, float* __restrict__ out, float* sm) {
    const int tid = threadIdx.x;
    float* sred = sm;

    float mloc = (tid < NBLK) ? __ldcg(&g_pmax[r * NBLK + tid]) : -3.0e38f;
    float m = wmax(mloc);
    if ((tid & 31) == 0) sred[tid >> 5] = m;
    __syncthreads();
    if (tid < 32) {
        float mm = (tid < NW) ? sred[tid] : -3.0e38f;
        mm = wmax(mm);
        if (tid == 0) sred[0] = mm;
    }
    __syncthreads();
    m = sred[0];
    __syncthreads();

    float sloc = (tid < NBLK) ? __ldcg(&g_psum[r * NBLK + tid]) * expf(mloc - m) : 0.0f;
    float ssum = wsum(sloc);
    if ((tid & 31) == 0) sred[tid >> 5] = ssum;
    __syncthreads();
    if (tid < 32) {
        float ss = (tid < NW) ? sred[tid] : 0.0f;
        ss = wsum(ss);
        if (tid == 0) sred[0] = m + logf(ss);
    }
    __syncthreads();
    float base = sred[0];

    const float* row = g_logits + (long)r * VV;
    float* orow = out + (long)r * VV;
    int v0 = half * VHALF;
    int v1 = half ? VV : VHALF;
    for (int v = v0 + tid; v < v1; v += NT) orow[v] = __ldcg(row + v) - base;
}

// ---------------- the mega kernel ----------------
__global__ __launch_bounds__(NT, 1) void mega_kernel(
    const int* __restrict__ input, const int* __restrict__ target,
    const float* __restrict__ eps, const float* __restrict__ emb,
    const float* __restrict__ encWih_f, const float* __restrict__ encWhh_f,
    const float* __restrict__ encbih_f, const float* __restrict__ encbhh_f,
    const float* __restrict__ encWih_b, const float* __restrict__ encWhh_b,
    const float* __restrict__ encbih_b, const float* __restrict__ encbhh_b,
    const float* __restrict__ decWih_f, const float* __restrict__ decWhh_f,
    const float* __restrict__ decbih_f, const float* __restrict__ decbhh_f,
    const float* __restrict__ decWih_b, const float* __restrict__ decWhh_b,
    const float* __restrict__ decbih_b, const float* __restrict__ decbhh_b,
    const float* __restrict__ h2m_W, const float* __restrict__ h2m_b,
    const float* __restrict__ h2v_W, const float* __restrict__ h2v_b,
    const float* __restrict__ l2h_W, const float* __restrict__ l2h_b,
    const float* __restrict__ attn_W, const float* __restrict__ attn_b,
    const float* __restrict__ comb_W, const float* __restrict__ comb_b,
    const float* __restrict__ out_W, const float* __restrict__ out_b,
    float* __restrict__ out)
{
    extern __shared__ float sm[];
    float* s_M = sm + SM_M;
    float* s_h = sm + SM_H;
    float* s_o = sm + SM_O;
    float* s_aw = sm + SM_AWV;
    float* s_s = sm + SM_S;

    const int tid = threadIdx.x;
    const int lane = tid & 31;
    const int warp = tid >> 5;
    unsigned tgt = 0, tgtE = 0, tgtP = 0;
    float* hbuf = (float*)g_h;

    if (blockIdx.x < S_CTAS) {
        // ================= SEQ ROLE (CTAs 0..39) =================
        const int grp = blockIdx.x / 20;
        const int cig = blockIdx.x % 20;
        const bool isGate = (warp >= 1);
        int gr = blockIdx.x * 15 + (warp - 1);
        int dir = 0, j = 0;
        if (isGate) { dir = gr / HD; j = gr % HD; }

        mini_prep(grp, cig, input, emb,
                  grp ? encWih_b : encWih_f, grp ? encbih_b : encbih_f);
        gbar_n(&g_barE[grp], 20, tgtE);

        float wA[30], wB[30];
        float ebr = 0, ebz = 0, ebn = 0;

        if (isGate) {
            const float* W = dir ? encWhh_b : encWhh_f;
            const float* bh = dir ? encbhh_b : encbhh_f;
#pragma unroll
            for (int i = 0; i < 10; i++) {
                int k = lane + 32 * i;
                bool ok = k < HD;
                wA[i]      = ok ? W[j * HD + k] : 0.0f;
                wA[10 + i] = ok ? W[(HD + j) * HD + k] : 0.0f;
                wA[20 + i] = ok ? W[(2 * HD + j) * HD + k] : 0.0f;
            }
            ebr = bh[j]; ebz = bh[HD + j]; ebn = bh[2 * HD + j];
        }

        // ---- encoder: 48 steps ----
        for (int t = 0; t < T_IN; t++) {
            if (t == 8) cta_wait(&g_prep, (unsigned)H_CTAS);
            const int p = t & 1, q = p ^ 1;
            float gi0 = 0, gi1 = 0, gi2 = 0;
            if (isGate && lane == 0) {
                const float* gi = g_enc_gi[grp] + t * 900;
                gi0 = gi[j]; gi1 = gi[HD + j]; gi2 = gi[2 * HD + j];
            }
            if (tid < 75) ((float4*)s_h)[tid] = __ldcg((const float4*)(hbuf + p * HH + grp * HD) + tid);
            __syncthreads();
            if (isGate) {
                float ar = 0, az = 0, an = 0;
#pragma unroll
                for (int i = 0; i < 10; i++) {
                    int k = lane + 32 * i;
                    if (k < HD) {
                        float hv = s_h[k];
                        ar = fmaf(wA[i], hv, ar);
                        az = fmaf(wA[10 + i], hv, az);
                        an = fmaf(wA[20 + i], hv, an);
                    }
                }
                ar = wsum(ar); az = wsum(az); an = wsum(an);
                if (lane == 0) {
                    float r = sigm(gi0 + ar + ebr);
                    float zg = sigm(gi1 + az + ebz);
                    float nn = tanhf(gi2 + r * (an + ebn));
                    float hn = (1.0f - zg) * nn + zg * s_h[j];
                    hbuf[q * HH + grp * HD + j] = hn;
                    g_enc_out[t * HH + grp * HD + j] = hn;
                }
            }
            gbar_n(&g_barE[grp], 20, tgtE);
        }

        gbar_n(&g_bar, S_CTAS, tgt);   // g_bar = 40

        // ---- preload decoder weights ----
        float dbhr = 0, dbhz = 0, dbhn = 0, dbir = 0, dbiz = 0, dbin = 0;
        if (isGate) {
            const float* Wh = dir ? decWhh_b : decWhh_f;
            const float* Wi = dir ? decWih_b : decWih_f;
#pragma unroll
            for (int i = 0; i < 10; i++) {
                int k = lane + 32 * i;
                bool ok = k < HD;
                wA[i]      = ok ? Wh[j * HD + k] : 0.0f;
                wA[10 + i] = ok ? Wh[(HD + j) * HD + k] : 0.0f;
                wA[20 + i] = ok ? Wh[(2 * HD + j) * HD + k] : 0.0f;
                wB[i]      = ok ? Wi[j * EE + k] : 0.0f;
                wB[10 + i] = ok ? Wi[(EE + j) * EE + k] : 0.0f;
                wB[20 + i] = ok ? Wi[(2 * EE + j) * EE + k] : 0.0f;
            }
            const float* bh = dir ? decbhh_b : decbhh_f;
            const float* bi = dir ? decbih_b : decbih_f;
            dbhr = bh[j]; dbhz = bh[HD + j]; dbhn = bh[2 * HD + j];
            dbir = bi[j]; dbiz = bi[HD + j]; dbin = bi[2 * HD + j];
        }

        // ---- VAE fused ----
        cta_wait(&g_pc, H_CTAS);
        for (int l = blockIdx.x; l < LL; l += S_CTAS) {
            for (int i = tid; i < HH; i += NT) s_h[i] = __ldcg(g_enc_out + l * HH + i);
            __syncthreads();
            for (int zi = warp; zi < ZZ; zi += NW) {
                float am = 0, av = 0;
                for (int k = lane; k < HH; k += 32) {
                    float e = s_h[k];
                    am = fmaf(h2m_W[zi * HH + k], e, am);
                    av = fmaf(h2v_W[zi * HH + k], e, av);
                }
                am = wsum(am); av = wsum(av);
                if (lane == 0) {
                    am += h2m_b[zi]; av += h2v_b[zi];
                    out[OFF_MEAN + l * ZZ + zi] = am;
                    out[OFF_LOGV + l * ZZ + zi] = av;
                    s_o[zi] = eps[l * ZZ + zi] * expf(0.5f * av) + am;
                }
            }
            __syncthreads();
            for (int e = tid; e < EE; e += NT) {
                float a = g_d[e];
#pragma unroll 4
                for (int k = 0; k < ZZ; k++) a = fmaf(s_o[k], g_C[k * EE + e], a);
                g_M[l * EE + e] = a;
            }
            __syncthreads();
        }
        gbar_n(&g_bar, S_CTAS, tgt);   // g_bar = 80

        // stage M into SMEM once
        for (int i = tid; i < LL * EE; i += NT) s_M[i] = __ldcg(g_M + i);

        // ---- decoder: 60 steps, 1 barrier each ----
        for (int t = 0; t < T_OUT; t++) {
            const int p = t & 1, q = p ^ 1;
            float cx = 0;
            if (tid < EE) cx = g_comb_x[t * EE + tid];
            if (tid < 150) ((float4*)s_h)[tid] = __ldcg((const float4*)(hbuf + p * HH) + tid);
            __syncthreads();

            // attention: weights from L1/global, h chunks register-cached per warp
            const float4* sh4 = (const float4*)s_h;
            float4 h4r[5];
#pragma unroll
            for (int i = 0; i < 5; i++) {
                int c = lane + 32 * i;
                h4r[i] = (c < 150) ? sh4[c] : make_float4(0.f, 0.f, 0.f, 0.f);
            }
#pragma unroll
            for (int rr = 0; rr < 4; rr++) {
                int l = warp + 16 * rr;
                if (l < LL) {
                    float axv = g_attn_x[t * LL + l];
                    const float4* aw4 = (const float4*)(attn_W + l * 900 + EE);
                    float a = 0;
#pragma unroll
                    for (int i = 0; i < 5; i++) {
                        int c = lane + 32 * i;
                        if (c < 150) {
                            float4 w = aw4[c];
                            a = fmaf(w.x, h4r[i].x, fmaf(w.y, h4r[i].y, fmaf(w.z, h4r[i].z, fmaf(w.w, h4r[i].w, a))));
                        }
                    }
                    a = wsum(a);
                    if (lane == 0) s_s[l] = a + axv;
                }
            }
            __syncthreads();

            float ghr = 0, ghz = 0, ghn = 0;
            if (warp == 0) {
                float v0 = s_s[lane];
                float v1 = (lane + 32 < LL) ? s_s[lane + 32] : -1e30f;
                float m = wmax(fmaxf(v0, v1));
                float e0 = expf(v0 - m);
                float e1 = (lane + 32 < LL) ? expf(v1 - m) : 0.0f;
                float inv = 1.0f / wsum(e0 + e1);
                s_aw[lane] = e0 * inv;
                if (lane + 32 < LL) s_aw[lane + 32] = e1 * inv;
            } else {
                const float* hs = s_h + dir * HD;
                float ar = 0, az = 0, an = 0;
#pragma unroll
                for (int i = 0; i < 10; i++) {
                    int k = lane + 32 * i;
                    if (k < HD) {
                        float hv = hs[k];
                        ar = fmaf(wA[i], hv, ar);
                        az = fmaf(wA[10 + i], hv, az);
                        an = fmaf(wA[20 + i], hv, an);
                    }
                }
                ar = wsum(ar); az = wsum(az); an = wsum(an);
                ghr = ar + dbhr; ghz = az + dbhz; ghn = an + dbhn;
            }
            __syncthreads();

            if (tid < EE) {
                float acc0 = cx, acc1 = 0.f;
#pragma unroll
                for (int l = 0; l < LL; l += 2) {
                    acc0 = fmaf(s_aw[l], s_M[l * EE + tid], acc0);
                    acc1 = fmaf(s_aw[l + 1], s_M[(l + 1) * EE + tid], acc1);
                }
                s_o[tid] = fmaxf(acc0 + acc1, 0.0f);
            }
            __syncthreads();

            if (isGate) {
                float br = 0, bz = 0, bn = 0;
#pragma unroll
                for (int i = 0; i < 10; i++) {
                    int k = lane + 32 * i;
                    if (k < EE) {
                        float ov = s_o[k];
                        br = fmaf(wB[i], ov, br);
                        bz = fmaf(wB[10 + i], ov, bz);
                        bn = fmaf(wB[20 + i], ov, bn);
                    }
                }
                br = wsum(br); bz = wsum(bz); bn = wsum(bn);
                if (lane == 0) {
                    float r = sigm(br + dbir + ghr);
                    float zg = sigm(bz + dbiz + ghz);
                    float nn = tanhf(bn + dbin + r * ghn);
                    float hn = (1.0f - zg) * nn + zg * s_h[dir * HD + j];
                    hbuf[q * HH + dir * HD + j] = hn;
                    g_hT[(dir * HD + j) * 64 + t] = hn;
                }
            }
            gbar_n(&g_bar, S_CTAS, tgt);
            if (blockIdx.x == 0 && tid == 0) strel(&g_step, (unsigned)(t + 1));
        }
    } else {
        // ================= HELPER ROLE (CTAs 40..147) =================
        phaseA(input, target, emb, encWih_f, encbih_f, encWih_b, encbih_b,
               attn_W, attn_b, comb_W, comb_b, l2h_W);
        gbar_n(&g_prep, H_CTAS, tgtP);

        prepC(comb_W, l2h_b);
        __syncthreads();
        if (tid == 0) redrel(&g_pc);

        // bands 0 (t0..29 @step30) and 1 (t30..49 @step50)
        int hid = blockIdx.x - S_CTAS;
        for (int idx = hid; idx < 2 * NBLK; idx += H_CTAS) {
            if (idx < NBLK) {
                cta_wait(&g_step, 30u);
                gemm_band_t<30>(sm, 0, idx, out_W, out_b);
                if (tid == 0) redrel(&g_bdone[0]);
            } else {
                cta_wait(&g_step, 50u);
                gemm_band_t<20>(sm, 30, idx - NBLK, out_W, out_b);
                if (tid == 0) redrel(&g_bdone[1]);
            }
        }
    }

    // ======== band 2 (t50..59, ALL CTAs, after full decoder) ========
    for (int blk = blockIdx.x; blk < NBLK; blk += G_CTAS) {
        cta_wait(&g_step, (unsigned)T_OUT);
        gemm_band_t<10>(sm, 50, blk, out_W, out_b);
        if (tid == 0) redrel(&g_bdone[2]);
    }

    // ======== log_softmax: 120 CTAs, half-row each ========
    if (blockIdx.x < 2 * T_OUT) {
        int r = blockIdx.x >> 1;
        int half = blockIdx.x & 1;
        int band = (r < 30) ? 0 : ((r < 50) ? 1 : 2);
        cta_wait(&g_bdone[band], NBLK);
        lsm_row_half(r, half, out, sm);
    }
}

extern "C" void kernel_launch(void* const* d_in, const int* in_sizes, int n_in,
                              void* d_out, int out_size) {
    const int* input = (const int*)d_in[0];
    const int* target = (const int*)d_in[1];
    const float* eps = (const float*)d_in[2];
    const float* emb = (const float*)d_in[3];
    const float* encWih_f = (const float*)d_in[4];
    const float* encWhh_f = (const float*)d_in[5];
    const float* encbih_f = (const float*)d_in[6];
    const float* encbhh_f = (const float*)d_in[7];
    const float* encWih_b = (const float*)d_in[8];
    const float* encWhh_b = (const float*)d_in[9];
    const float* encbih_b = (const float*)d_in[10];
    const float* encbhh_b = (const float*)d_in[11];
    const float* decWih_f = (const float*)d_in[12];
    const float* decWhh_f = (const float*)d_in[13];
    const float* decbih_f = (const float*)d_in[14];
    const float* decbhh_f = (const float*)d_in[15];
    const float* decWih_b = (const float*)d_in[16];
    const float* decWhh_b = (const float*)d_in[17];
    const float* decbih_b = (const float*)d_in[18];
    const float* decbhh_b = (const float*)d_in[19];
    const float* h2m_W = (const float*)d_in[20];
    const float* h2m_b = (const float*)d_in[21];
    const float* h2v_W = (const float*)d_in[22];
    const float* h2v_b = (const float*)d_in[23];
    const float* l2h_W = (const float*)d_in[24];
    const float* l2h_b = (const float*)d_in[25];
    const float* attn_W = (const float*)d_in[26];
    const float* attn_b = (const float*)d_in[27];
    const float* comb_W = (const float*)d_in[28];
    const float* comb_b = (const float*)d_in[29];
    const float* out_W = (const float*)d_in[30];
    const float* out_b = (const float*)d_in[31];
    float* out = (float*)d_out;

    cudaFuncSetAttribute(mega_kernel, cudaFuncAttributeMaxDynamicSharedMemorySize,
                         SMEM_BYTES);

    init_kernel<<<1, 256>>>();
    mega_kernel<<<G_CTAS, NT, SMEM_BYTES>>>(
        input, target, eps, emb,
        encWih_f, encWhh_f, encbih_f, encbhh_f,
        encWih_b, encWhh_b, encbih_b, encbhh_b,
        decWih_f, decWhh_f, decbih_f, decbhh_f,
        decWih_b, decWhh_b, decbih_b, decbhh_b,
        h2m_W, h2m_b, h2v_W, h2v_b, l2h_W, l2h_b,
        attn_W, attn_b, comb_W, comb_b, out_W, out_b, out);
}